// round 4
// baseline (speedup 1.0000x reference)
#include <cuda_runtime.h>
#include <cuda_bf16.h>
#include <cuda_fp16.h>
#include <math_constants.h>

// ---------------------------------------------------------------------------
// GAT_50861002719235: 3-layer GAT, N=50000, E=1.6M, H=4, D=32/32/47
// CSR-by-dst gather; warp-per-node 4-head aggregation; fp16 feature storage.
// ---------------------------------------------------------------------------

#define NN 50000
#define EE 1600000
#define HH 4
#define FIN 100
#define HD 128          // H*D layers 0/1
#define CC 47
#define DP 48           // padded D for layer 2
#define HCP 192         // padded H*D layer 2 (4*48)
#define NEG_SLOPE 0.2f

// ---- scratch ----
__device__ int    g_row_ptr[NN + 1];
__device__ int    g_cursor[NN];
__device__ int    g_col_src[EE];
__device__ __half g_fsh[NN * HCP];   // transformed features, fp16 (gather operand)
__device__ float  g_h [NN * HCP];    // finalized output / next input (fp32)
__device__ float  g_el[NN * HH];     // [n][h] float4-aligned
__device__ float  g_er[NN * HH];     // [n][h]
__device__ float  g_maxel[HH];       // per-head global max of el

__device__ __forceinline__ float lrelu(float x) { return (x >= 0.f) ? x : NEG_SLOPE * x; }
__device__ __forceinline__ float4 lrelu4(float4 v) {
    return make_float4(lrelu(v.x), lrelu(v.y), lrelu(v.z), lrelu(v.w));
}

// ---------------------------------------------------------------------------
// CSR build
// ---------------------------------------------------------------------------
__global__ void zero_counts_k() {
    int i = blockIdx.x * blockDim.x + threadIdx.x;
    if (i < NN) g_cursor[i] = 0;
}
__global__ void count_k(const int* __restrict__ dst) {
    int e = blockIdx.x * blockDim.x + threadIdx.x;
    if (e < EE) atomicAdd(&g_cursor[dst[e]], 1);
}
__global__ void scan_k() {
    __shared__ int sh[1024];
    const int chunk = (NN + 1023) / 1024;
    int t = threadIdx.x;
    int base = t * chunk;
    int local = 0;
    for (int i = 0; i < chunk; i++) { int idx = base + i; if (idx < NN) local += g_cursor[idx]; }
    sh[t] = local;
    __syncthreads();
    for (int o = 1; o < 1024; o <<= 1) {
        int v = (t >= o) ? sh[t - o] : 0;
        __syncthreads(); sh[t] += v; __syncthreads();
    }
    int run = (t > 0) ? sh[t - 1] : 0;
    for (int i = 0; i < chunk; i++) {
        int idx = base + i;
        if (idx < NN) { int c = g_cursor[idx]; g_row_ptr[idx] = run; g_cursor[idx] = run; run += c; }
    }
    if (t == 1023) g_row_ptr[NN] = sh[1023];
}
__global__ void fill_k(const int* __restrict__ src, const int* __restrict__ dst) {
    int e = blockIdx.x * blockDim.x + threadIdx.x;
    if (e < EE) { int p = atomicAdd(&g_cursor[dst[e]], 1); g_col_src[p] = src[e]; }
}

// ---------------------------------------------------------------------------
// GEMM layers 0/1: out_h[n,c] = (half) sum_k A[n,k]*W[k,c].  32-row tile.
// ---------------------------------------------------------------------------
template<int K, int COLS, int TPB>
__global__ void gemm_k(const float* __restrict__ A, const float* __restrict__ W,
                       __half* __restrict__ out) {
    __shared__ float sh[32 * K];
    int n0 = blockIdx.x * 32;
    const int nv = 32 * K / 4;
    const float4* A4 = (const float4*)(A + (long)n0 * K);
    float4* sh4 = (float4*)sh;
    if (n0 + 32 <= NN) {
        for (int idx = threadIdx.x; idx < nv; idx += TPB) sh4[idx] = A4[idx];
    } else {
        for (int idx = threadIdx.x; idx < nv; idx += TPB) {
            int n = n0 + (idx * 4) / K;
            sh4[idx] = (n < NN) ? A4[idx] : make_float4(0.f, 0.f, 0.f, 0.f);
        }
    }
    __syncthreads();
    int c = threadIdx.x;
    if (c >= COLS) return;
    float acc[32];
#pragma unroll
    for (int r = 0; r < 32; r++) acc[r] = 0.f;
    for (int k0 = 0; k0 < K; k0 += 4) {
        float w0 = W[(k0 + 0) * COLS + c];
        float w1 = W[(k0 + 1) * COLS + c];
        float w2 = W[(k0 + 2) * COLS + c];
        float w3 = W[(k0 + 3) * COLS + c];
#pragma unroll
        for (int r = 0; r < 32; r++) {
            float4 a = *(const float4*)&sh[r * K + k0];
            acc[r] += a.x * w0 + a.y * w1 + a.z * w2 + a.w * w3;
        }
    }
    int nmax = min(32, NN - n0);
    for (int r = 0; r < nmax; r++)
        out[(long)(n0 + r) * COLS + c] = __float2half_rn(acc[r]);
}

// GEMM layer 2, padded output [n][4][48] (half); pad col (d=47) zeroed.
__global__ void gemm2_k(const float* __restrict__ A, const float* __restrict__ W,
                        __half* __restrict__ out) {
    const int K = HD, COLS = HH * CC, TPB = 192;
    __shared__ float sh[32 * K];
    int n0 = blockIdx.x * 32;
    const int nv = 32 * K / 4;
    const float4* A4 = (const float4*)(A + (long)n0 * K);
    float4* sh4 = (float4*)sh;
    if (n0 + 32 <= NN) {
        for (int idx = threadIdx.x; idx < nv; idx += TPB) sh4[idx] = A4[idx];
    } else {
        for (int idx = threadIdx.x; idx < nv; idx += TPB) {
            int n = n0 + (idx * 4) / K;
            sh4[idx] = (n < NN) ? A4[idx] : make_float4(0.f, 0.f, 0.f, 0.f);
        }
    }
    __syncthreads();
    int c = threadIdx.x;
    int nmax = min(32, NN - n0);
    if (c >= COLS) {
        if (c < COLS + HH) {
            int h = c - COLS;
            for (int r = 0; r < nmax; r++)
                out[(long)(n0 + r) * HCP + h * DP + (DP - 1)] = __float2half_rn(0.f);
        }
        return;
    }
    float acc[32];
#pragma unroll
    for (int r = 0; r < 32; r++) acc[r] = 0.f;
    for (int k0 = 0; k0 < K; k0 += 4) {
        float w0 = W[(k0 + 0) * COLS + c];
        float w1 = W[(k0 + 1) * COLS + c];
        float w2 = W[(k0 + 2) * COLS + c];
        float w3 = W[(k0 + 3) * COLS + c];
#pragma unroll
        for (int r = 0; r < 32; r++) {
            float4 a = *(const float4*)&sh[r * K + k0];
            acc[r] += a.x * w0 + a.y * w1 + a.z * w2 + a.w * w3;
        }
    }
    int cp = (c / CC) * DP + (c % CC);
    for (int r = 0; r < nmax; r++)
        out[(long)(n0 + r) * HCP + cp] = __float2half_rn(acc[r]);
}

// ---------------------------------------------------------------------------
// elr layers 0/1: warp per node; lane owns 4 half dims (uint2 load).
// ---------------------------------------------------------------------------
__global__ void elr_node_k(const __half* __restrict__ fsh, const float* __restrict__ al,
                           const float* __restrict__ ar) {
    int w = (blockIdx.x * blockDim.x + threadIdx.x) >> 5;
    int lane = threadIdx.x & 31;
    if (w >= NN) return;
    int n = w;
    uint2 u = ((const uint2*)fsh)[(long)n * 32 + lane];
    float2 f0 = __half22float2(*(__half2*)&u.x);
    float2 f1 = __half22float2(*(__half2*)&u.y);
    float4 a  = ((const float4*)al)[lane];
    float4 b  = ((const float4*)ar)[lane];
    float sl = f0.x * a.x + f0.y * a.y + f1.x * a.z + f1.y * a.w;
    float sr = f0.x * b.x + f0.y * b.y + f1.x * b.z + f1.y * b.w;
#pragma unroll
    for (int o = 1; o < 8; o <<= 1) {
        sl += __shfl_xor_sync(0xffffffffu, sl, o);
        sr += __shfl_xor_sync(0xffffffffu, sr, o);
    }
    if ((lane & 7) == 0) {
        int h = lane >> 3;
        g_el[n * HH + h] = sl;
        g_er[n * HH + h] = sr;
    }
}

// elr layer 2: warp per (n,h), padded half fs (stride 192).
__global__ void elr2_k(const __half* __restrict__ fsh, const float* __restrict__ al,
                       const float* __restrict__ ar) {
    int w = (blockIdx.x * blockDim.x + threadIdx.x) >> 5;
    int lane = threadIdx.x & 31;
    if (w >= NN * HH) return;
    int n = w >> 2, h = w & 3;
    float sl = 0.f, sr = 0.f;
    for (int d = lane; d < CC; d += 32) {
        float v = __half2float(fsh[(long)n * HCP + h * DP + d]);
        sl += v * al[h * CC + d];
        sr += v * ar[h * CC + d];
    }
#pragma unroll
    for (int o = 16; o; o >>= 1) {
        sl += __shfl_xor_sync(0xffffffffu, sl, o);
        sr += __shfl_xor_sync(0xffffffffu, sr, o);
    }
    if (lane == 0) { g_el[n * HH + h] = sl; g_er[n * HH + h] = sr; }
}

// per-head global max of el ([n][4] layout), single block.
__global__ void maxel_k() {
    __shared__ float4 sm[1024];
    const float4* el4 = (const float4*)g_el;
    float4 m = make_float4(-CUDART_INF_F, -CUDART_INF_F, -CUDART_INF_F, -CUDART_INF_F);
    for (int n = threadIdx.x; n < NN; n += 1024) {
        float4 v = el4[n];
        m.x = fmaxf(m.x, v.x); m.y = fmaxf(m.y, v.y);
        m.z = fmaxf(m.z, v.z); m.w = fmaxf(m.w, v.w);
    }
    sm[threadIdx.x] = m;
    __syncthreads();
    for (int o = 512; o >= 1; o >>= 1) {
        if (threadIdx.x < o) {
            float4 a = sm[threadIdx.x], b = sm[threadIdx.x + o];
            sm[threadIdx.x] = make_float4(fmaxf(a.x, b.x), fmaxf(a.y, b.y),
                                          fmaxf(a.z, b.z), fmaxf(a.w, b.w));
        }
        __syncthreads();
    }
    if (threadIdx.x < 4) g_maxel[threadIdx.x] = ((const float*)&sm[0])[threadIdx.x];
}

// ---------------------------------------------------------------------------
// Gather layers 0/1: warp per node, 4 heads. fp16 row = 32 lanes x uint2
// (LDG.64, 256B/row). fp32 accumulate.
// ---------------------------------------------------------------------------
template<bool RELU>
__global__ void gather_node_k(const __half* __restrict__ fsh, float* __restrict__ out) {
    __shared__ float4 sm_ex[8][32];
    int wib = threadIdx.x >> 5;
    int w = blockIdx.x * 8 + wib;
    int lane = threadIdx.x & 31;
    if (w >= NN) return;
    int n = w;
    int myh = lane >> 3;
    int beg = g_row_ptr[n], end = g_row_ptr[n + 1];
    float4 er4 = ((const float4*)g_er)[n];
    float4 mx4 = *(const float4*)g_maxel;
    float4 m4 = lrelu4(make_float4(mx4.x + er4.x, mx4.y + er4.y, mx4.z + er4.z, mx4.w + er4.w));

    const uint2* fs2 = (const uint2*)fsh;
    float4 acc = make_float4(0.f, 0.f, 0.f, 0.f);
    float4 ssum = make_float4(0.f, 0.f, 0.f, 0.f);

    for (int i0 = beg; i0 < end; i0 += 32) {
        int i = i0 + lane;
        int s = 0;
        float4 ex = make_float4(0.f, 0.f, 0.f, 0.f);
        if (i < end) {
            s = g_col_src[i];
            float4 el4 = ((const float4*)g_el)[s];
            float4 e4 = lrelu4(make_float4(el4.x + er4.x, el4.y + er4.y,
                                           el4.z + er4.z, el4.w + er4.w));
            ex = make_float4(__expf(e4.x - m4.x), __expf(e4.y - m4.y),
                             __expf(e4.z - m4.z), __expf(e4.w - m4.w));
            ssum.x += ex.x; ssum.y += ex.y; ssum.z += ex.z; ssum.w += ex.w;
        }
        sm_ex[wib][lane] = ex;
        __syncwarp();
        int cnt = min(32, end - i0);
        const float* exbase = (const float*)&sm_ex[wib][0] + myh;
        if (cnt == 32) {
#pragma unroll
            for (int j = 0; j < 32; j++) {
                int sj = __shfl_sync(0xffffffffu, s, j);
                float exj = exbase[j * 4];
                uint2 u = fs2[(long)sj * 32 + lane];
                float2 f0 = __half22float2(*(__half2*)&u.x);
                float2 f1 = __half22float2(*(__half2*)&u.y);
                acc.x += exj * f0.x; acc.y += exj * f0.y;
                acc.z += exj * f1.x; acc.w += exj * f1.y;
            }
        } else {
            for (int j = 0; j < cnt; j++) {
                int sj = __shfl_sync(0xffffffffu, s, j);
                float exj = exbase[j * 4];
                uint2 u = fs2[(long)sj * 32 + lane];
                float2 f0 = __half22float2(*(__half2*)&u.x);
                float2 f1 = __half22float2(*(__half2*)&u.y);
                acc.x += exj * f0.x; acc.y += exj * f0.y;
                acc.z += exj * f1.x; acc.w += exj * f1.y;
            }
        }
        __syncwarp();
    }
#pragma unroll
    for (int o = 16; o; o >>= 1) {
        ssum.x += __shfl_xor_sync(0xffffffffu, ssum.x, o);
        ssum.y += __shfl_xor_sync(0xffffffffu, ssum.y, o);
        ssum.z += __shfl_xor_sync(0xffffffffu, ssum.z, o);
        ssum.w += __shfl_xor_sync(0xffffffffu, ssum.w, o);
    }
    float s_my = (myh == 0) ? ssum.x : (myh == 1) ? ssum.y : (myh == 2) ? ssum.z : ssum.w;
    float inv = (s_my > 0.f) ? 1.f / s_my : 0.f;
    float4 o4 = make_float4(acc.x * inv, acc.y * inv, acc.z * inv, acc.w * inv);
    if (RELU) {
        o4.x = fmaxf(o4.x, 0.f); o4.y = fmaxf(o4.y, 0.f);
        o4.z = fmaxf(o4.z, 0.f); o4.w = fmaxf(o4.w, 0.f);
    }
    ((float4*)out)[(long)n * 32 + lane] = o4;
}

// ---------------------------------------------------------------------------
// Gather layer 2 (padded D=48, half): row = 192 halves = 48 uint2.
// Lane covers uint2 idx lane, and lane+32 for lane<16.
// ---------------------------------------------------------------------------
__global__ void gather2_node_k(const __half* __restrict__ fsh, float* __restrict__ out) {
    __shared__ float4 sm_ex[8][32];
    int wib = threadIdx.x >> 5;
    int w = blockIdx.x * 8 + wib;
    int lane = threadIdx.x & 31;
    if (w >= NN) return;
    int n = w;
    int ha = lane / 12;
    int hb = (lane + 32) / 12;
    bool hasb = (lane < 16);
    int beg = g_row_ptr[n], end = g_row_ptr[n + 1];
    float4 er4 = ((const float4*)g_er)[n];
    float4 mx4 = *(const float4*)g_maxel;
    float4 m4 = lrelu4(make_float4(mx4.x + er4.x, mx4.y + er4.y, mx4.z + er4.z, mx4.w + er4.w));

    const uint2* fs2 = (const uint2*)fsh;
    float4 acca = make_float4(0.f, 0.f, 0.f, 0.f);
    float4 accb = make_float4(0.f, 0.f, 0.f, 0.f);
    float4 ssum = make_float4(0.f, 0.f, 0.f, 0.f);

    for (int i0 = beg; i0 < end; i0 += 32) {
        int i = i0 + lane;
        int s = 0;
        float4 ex = make_float4(0.f, 0.f, 0.f, 0.f);
        if (i < end) {
            s = g_col_src[i];
            float4 el4 = ((const float4*)g_el)[s];
            float4 e4 = lrelu4(make_float4(el4.x + er4.x, el4.y + er4.y,
                                           el4.z + er4.z, el4.w + er4.w));
            ex = make_float4(__expf(e4.x - m4.x), __expf(e4.y - m4.y),
                             __expf(e4.z - m4.z), __expf(e4.w - m4.w));
            ssum.x += ex.x; ssum.y += ex.y; ssum.z += ex.z; ssum.w += ex.w;
        }
        sm_ex[wib][lane] = ex;
        __syncwarp();
        int cnt = min(32, end - i0);
        const float* exb = (const float*)&sm_ex[wib][0];
        for (int j = 0; j < cnt; j++) {
            int sj = __shfl_sync(0xffffffffu, s, j);
            long rb = (long)sj * 48;
            float exja = exb[j * 4 + ha];
            uint2 u = fs2[rb + lane];
            float2 f0 = __half22float2(*(__half2*)&u.x);
            float2 f1 = __half22float2(*(__half2*)&u.y);
            acca.x += exja * f0.x; acca.y += exja * f0.y;
            acca.z += exja * f1.x; acca.w += exja * f1.y;
            if (hasb) {
                float exjb = exb[j * 4 + hb];
                uint2 u2 = fs2[rb + 32 + lane];
                float2 g0 = __half22float2(*(__half2*)&u2.x);
                float2 g1 = __half22float2(*(__half2*)&u2.y);
                accb.x += exjb * g0.x; accb.y += exjb * g0.y;
                accb.z += exjb * g1.x; accb.w += exjb * g1.y;
            }
        }
        __syncwarp();
    }
#pragma unroll
    for (int o = 16; o; o >>= 1) {
        ssum.x += __shfl_xor_sync(0xffffffffu, ssum.x, o);
        ssum.y += __shfl_xor_sync(0xffffffffu, ssum.y, o);
        ssum.z += __shfl_xor_sync(0xffffffffu, ssum.z, o);
        ssum.w += __shfl_xor_sync(0xffffffffu, ssum.w, o);
    }
    float sa = (ha == 0) ? ssum.x : (ha == 1) ? ssum.y : (ha == 2) ? ssum.z : ssum.w;
    float inva = (sa > 0.f) ? 1.f / sa : 0.f;
    ((float4*)out)[(long)n * 48 + lane] =
        make_float4(acca.x * inva, acca.y * inva, acca.z * inva, acca.w * inva);
    if (hasb) {
        float sb = (hb == 0) ? ssum.x : (hb == 1) ? ssum.y : (hb == 2) ? ssum.z : ssum.w;
        float invb = (sb > 0.f) ? 1.f / sb : 0.f;
        ((float4*)out)[(long)n * 48 + 32 + lane] =
            make_float4(accb.x * invb, accb.y * invb, accb.z * invb, accb.w * invb);
    }
}

// ---------------------------------------------------------------------------
// Final: mean over heads (padded stride 48) + log_softmax over 47.
// ---------------------------------------------------------------------------
__global__ void final_k(const float* __restrict__ hin, float* __restrict__ out) {
    int w = (blockIdx.x * blockDim.x + threadIdx.x) >> 5;
    int lane = threadIdx.x & 31;
    if (w >= NN) return;
    int n = w;
    float v0 = 0.f, v1 = 0.f;
    int c0 = lane, c1 = lane + 32;
    if (c0 < CC) {
#pragma unroll
        for (int h = 0; h < HH; h++) v0 += hin[(long)n * HCP + h * DP + c0];
        v0 *= 0.25f;
    }
    if (c1 < CC) {
#pragma unroll
        for (int h = 0; h < HH; h++) v1 += hin[(long)n * HCP + h * DP + c1];
        v1 *= 0.25f;
    }
    float a = (c0 < CC) ? v0 : -CUDART_INF_F;
    float b = (c1 < CC) ? v1 : -CUDART_INF_F;
    float m = fmaxf(a, b);
#pragma unroll
    for (int o = 16; o; o >>= 1) m = fmaxf(m, __shfl_xor_sync(0xffffffffu, m, o));
    float s = 0.f;
    if (c0 < CC) s += __expf(v0 - m);
    if (c1 < CC) s += __expf(v1 - m);
#pragma unroll
    for (int o = 16; o; o >>= 1) s += __shfl_xor_sync(0xffffffffu, s, o);
    float lse = m + logf(s);
    if (c0 < CC) out[(long)n * CC + c0] = v0 - lse;
    if (c1 < CC) out[(long)n * CC + c1] = v1 - lse;
}

// ---------------------------------------------------------------------------
extern "C" void kernel_launch(void* const* d_in, const int* in_sizes, int n_in,
                              void* d_out, int out_size) {
    const float* x   = (const float*)d_in[0];
    const float* W0  = (const float*)d_in[1];
    const float* al0 = (const float*)d_in[2];
    const float* ar0 = (const float*)d_in[3];
    const float* W1  = (const float*)d_in[4];
    const float* al1 = (const float*)d_in[5];
    const float* ar1 = (const float*)d_in[6];
    const float* W2  = (const float*)d_in[7];
    const float* al2 = (const float*)d_in[8];
    const float* ar2 = (const float*)d_in[9];
    const int*   src = (const int*)d_in[10];
    const int*   dst = (const int*)d_in[11];
    float* out = (float*)d_out;

    __half* fsh = nullptr; float* hbuf = nullptr;
    cudaGetSymbolAddress((void**)&fsh,  g_fsh);
    cudaGetSymbolAddress((void**)&hbuf, g_h);

    // ---- CSR build ----
    zero_counts_k<<<(NN + 255) / 256, 256>>>();
    count_k<<<(EE + 255) / 256, 256>>>(dst);
    scan_k<<<1, 1024>>>();
    fill_k<<<(EE + 255) / 256, 256>>>(src, dst);

    const int gemm_blocks = (NN + 31) / 32;
    const int node_blocks = (NN + 7) / 8;
    const int nh_blocks   = (NN * HH * 32 + 255) / 256;

    // ---- layer 0: x[N,100] -> h[N,128] ----
    gemm_k<FIN, HD, 128><<<gemm_blocks, 128>>>(x, W0, fsh);
    elr_node_k<<<node_blocks, 256>>>(fsh, al0, ar0);
    maxel_k<<<1, 1024>>>();
    gather_node_k<true><<<node_blocks, 256>>>(fsh, hbuf);

    // ---- layer 1 ----
    gemm_k<HD, HD, 128><<<gemm_blocks, 128>>>(hbuf, W1, fsh);
    elr_node_k<<<node_blocks, 256>>>(fsh, al1, ar1);
    maxel_k<<<1, 1024>>>();
    gather_node_k<true><<<node_blocks, 256>>>(fsh, hbuf);

    // ---- layer 2 (padded 4x48, half) ----
    gemm2_k<<<gemm_blocks, 192>>>(hbuf, W2, fsh);
    elr2_k<<<nh_blocks, 256>>>(fsh, al2, ar2);
    maxel_k<<<1, 1024>>>();
    gather2_node_k<<<node_blocks, 256>>>(fsh, hbuf);

    // ---- head mean + log_softmax ----
    final_k<<<node_blocks, 256>>>(hbuf, out);
}